// round 1
// baseline (speedup 1.0000x reference)
#include <cuda_runtime.h>
#include <math.h>

// Problem constants (fixed by the dataset)
#define NN 100000   // nodes
#define DD 128      // feature dim (= hidden dim)

// ---------------- scratch (static device globals; no allocation) ----------------
__device__ __align__(16) float g_agg[NN * DD];
__device__ __align__(16) float g_x1[NN * DD];
__device__ __align__(16) float g_x2[NN * DD];
__device__ float g_cnt[NN];
__device__ float g_bnsum[DD];
__device__ float g_bnsq[DD];
__device__ float g_scale[DD];
__device__ float g_shift[DD];

// ---------------- zero scratch ----------------
__global__ void zero_kernel(int zero_cnt) {
    int i = blockIdx.x * blockDim.x + threadIdx.x;
    if (i < NN * DD / 4) ((float4*)g_agg)[i] = make_float4(0.f, 0.f, 0.f, 0.f);
    if (i < DD) { g_bnsum[i] = 0.f; g_bnsq[i] = 0.f; }
    if (zero_cnt && i < NN) g_cnt[i] = 0.f;
}

// ---------------- edge scatter: agg[dst] += x[src], cnt[dst] += 1 ----------------
// One warp per edge; each lane moves a float4 (16B) slice of the 512B row.
__global__ void scatter_kernel(const float* __restrict__ x,
                               const int* __restrict__ src,
                               const int* __restrict__ dst,
                               int E, int do_cnt) {
    int gw = (blockIdx.x * blockDim.x + threadIdx.x) >> 5;
    int lane = threadIdx.x & 31;
    if (gw >= E) return;
    int s = __ldg(&src[gw]);
    int d = __ldg(&dst[gw]);
    float4 v = ((const float4*)x)[(size_t)s * 32 + lane];
    float* p = g_agg + (size_t)d * DD + lane * 4;
    asm volatile("red.global.add.v4.f32 [%0], {%1,%2,%3,%4};"
                 :: "l"(p), "f"(v.x), "f"(v.y), "f"(v.z), "f"(v.w) : "memory");
    if (do_cnt && lane == 0) atomicAdd(&g_cnt[d], 1.0f);
}

// ---------------- fused SAGE layer ----------------
// out = L2normalize( (agg/max(cnt,1)) @ Wl + bl + x @ Wr ), accumulates BN sum/sumsq.
// Block: 128 threads, 64-node tile, each thread computes an 8(nodes)x8(h) register tile.
// Smem: Wl[128x128] + Wr[128x128] + A[128x64] + X[128x64] = 192 KB dynamic.
__global__ void sage_kernel(const float* __restrict__ x_in,
                            const float* __restrict__ Wl,
                            const float* __restrict__ bl,
                            const float* __restrict__ Wr,
                            float* __restrict__ x_out,
                            int nnodes) {
    extern __shared__ float sm[];
    float* Wl_s = sm;                 // 16384 floats, [d][h]
    float* Wr_s = sm + 16384;         // 16384 floats
    float* A_s  = sm + 32768;         // 8192 floats, [d][n] (n fastest)
    float* X_s  = sm + 40960;         // 8192 floats

    const int tid = threadIdx.x;      // 128 threads
    const int base = blockIdx.x * 64;

    // Stage weight matrices (row-major [d][h], straight copy, coalesced)
    const float4* Wl4 = (const float4*)Wl;
    const float4* Wr4 = (const float4*)Wr;
    float4* Wl_s4 = (float4*)Wl_s;
    float4* Wr_s4 = (float4*)Wr_s;
#pragma unroll
    for (int i = 0; i < 32; i++) {
        int q = tid + i * 128;
        Wl_s4[q] = Wl4[q];
        Wr_s4[q] = Wr4[q];
    }

    // Stage A (= agg/cnt) and X transposed into [d][n]
#pragma unroll
    for (int i = 0; i < 16; i++) {
        int q = tid + i * 128;        // 0..2047 (float4 granules)
        int n = q >> 5;               // node within tile (0..63)
        int d4 = q & 31;              // float4 index along d
        int gn = base + n;
        float inv = 0.f;
        float4 a = make_float4(0.f, 0.f, 0.f, 0.f);
        float4 xv = make_float4(0.f, 0.f, 0.f, 0.f);
        if (gn < nnodes) {
            inv = 1.0f / fmaxf(g_cnt[gn], 1.0f);
            a  = ((const float4*)g_agg)[(size_t)gn * 32 + d4];
            xv = ((const float4*)x_in)[(size_t)gn * 32 + d4];
        }
        int db = d4 * 4;
        A_s[(db + 0) * 64 + n] = a.x * inv;
        A_s[(db + 1) * 64 + n] = a.y * inv;
        A_s[(db + 2) * 64 + n] = a.z * inv;
        A_s[(db + 3) * 64 + n] = a.w * inv;
        X_s[(db + 0) * 64 + n] = xv.x;
        X_s[(db + 1) * 64 + n] = xv.y;
        X_s[(db + 2) * 64 + n] = xv.z;
        X_s[(db + 3) * 64 + n] = xv.w;
    }
    __syncthreads();

    const int tx = tid & 15;          // h tile (16 tiles of 8)
    const int ty = tid >> 4;          // n tile (8 tiles of 8)
    const int h0 = tx * 8;
    const int n0 = ty * 8;

    float acc[64];
#pragma unroll
    for (int i = 0; i < 64; i++) acc[i] = 0.f;

#pragma unroll 2
    for (int d = 0; d < 128; d++) {
        float4 wl0 = *(const float4*)(Wl_s + d * 128 + h0);
        float4 wl1 = *(const float4*)(Wl_s + d * 128 + h0 + 4);
        float4 wr0 = *(const float4*)(Wr_s + d * 128 + h0);
        float4 wr1 = *(const float4*)(Wr_s + d * 128 + h0 + 4);
        float4 a0  = *(const float4*)(A_s + d * 64 + n0);
        float4 a1  = *(const float4*)(A_s + d * 64 + n0 + 4);
        float4 xx0 = *(const float4*)(X_s + d * 64 + n0);
        float4 xx1 = *(const float4*)(X_s + d * 64 + n0 + 4);
        float ww[8] = {wl0.x, wl0.y, wl0.z, wl0.w, wl1.x, wl1.y, wl1.z, wl1.w};
        float uu[8] = {wr0.x, wr0.y, wr0.z, wr0.w, wr1.x, wr1.y, wr1.z, wr1.w};
        float aa[8] = {a0.x, a0.y, a0.z, a0.w, a1.x, a1.y, a1.z, a1.w};
        float xv[8] = {xx0.x, xx0.y, xx0.z, xx0.w, xx1.x, xx1.y, xx1.z, xx1.w};
#pragma unroll
        for (int ni = 0; ni < 8; ni++)
#pragma unroll
            for (int hi = 0; hi < 8; hi++)
                acc[ni * 8 + hi] += aa[ni] * ww[hi] + xv[ni] * uu[hi];
    }

    // Epilogue: +bias, L2-normalize row (reduction across the 16 tx lanes), write,
    // and gather BN partial sums.
    float bv[8];
#pragma unroll
    for (int hi = 0; hi < 8; hi++) bv[hi] = bl[h0 + hi];

    float p1[8], p2[8];
#pragma unroll
    for (int hi = 0; hi < 8; hi++) { p1[hi] = 0.f; p2[hi] = 0.f; }

#pragma unroll
    for (int ni = 0; ni < 8; ni++) {
        float v[8];
        float ss = 0.f;
#pragma unroll
        for (int hi = 0; hi < 8; hi++) {
            v[hi] = acc[ni * 8 + hi] + bv[hi];
            ss += v[hi] * v[hi];
        }
        // reduce across the 16 threads (same ty) that share this node row
#pragma unroll
        for (int m = 1; m < 16; m <<= 1) ss += __shfl_xor_sync(0xffffffffu, ss, m);
        float inv = 1.0f / fmaxf(sqrtf(ss), 1e-12f);
        int gn = base + n0 + ni;
        if (gn < nnodes) {
            float4 o0 = make_float4(v[0] * inv, v[1] * inv, v[2] * inv, v[3] * inv);
            float4 o1 = make_float4(v[4] * inv, v[5] * inv, v[6] * inv, v[7] * inv);
            float4* op = (float4*)(x_out + (size_t)gn * DD + h0);
            op[0] = o0;
            op[1] = o1;
#pragma unroll
            for (int hi = 0; hi < 8; hi++) {
                float vo = v[hi] * inv;
                p1[hi] += vo;
                p2[hi] += vo * vo;
            }
        }
    }

    // Block-level BN partial reduction (reuse A_s/X_s), then one atomic per h.
    __syncthreads();
#pragma unroll
    for (int hi = 0; hi < 8; hi++) {
        A_s[(h0 + hi) * 8 + ty] = p1[hi];
        X_s[(h0 + hi) * 8 + ty] = p2[hi];
    }
    __syncthreads();
    {
        float s1 = 0.f, s2 = 0.f;
#pragma unroll
        for (int t = 0; t < 8; t++) {
            s1 += A_s[tid * 8 + t];
            s2 += X_s[tid * 8 + t];
        }
        atomicAdd(&g_bnsum[tid], s1);
        atomicAdd(&g_bnsq[tid], s2);
    }
}

// ---------------- BN params from accumulated sums ----------------
__global__ void bnparams_kernel(const float* __restrict__ g,
                                const float* __restrict__ b,
                                float invN) {
    int h = threadIdx.x;
    float mean = g_bnsum[h] * invN;
    float var = g_bnsq[h] * invN - mean * mean;
    float sc = g[h] / sqrtf(var + 1e-5f);
    g_scale[h] = sc;
    g_shift[h] = b[h] - mean * sc;
}

// ---------------- apply BN + ReLU in place ----------------
__global__ void bnrelu_kernel(float* __restrict__ x, int total4) {
    int i = blockIdx.x * blockDim.x + threadIdx.x;
    if (i >= total4) return;
    int h4 = i & 31;
    float4 v = ((float4*)x)[i];
    float4 sc = ((const float4*)g_scale)[h4];
    float4 sh = ((const float4*)g_shift)[h4];
    v.x = fmaxf(fmaf(v.x, sc.x, sh.x), 0.f);
    v.y = fmaxf(fmaf(v.y, sc.y, sh.y), 0.f);
    v.z = fmaxf(fmaf(v.z, sc.z, sh.z), 0.f);
    v.w = fmaxf(fmaf(v.w, sc.w, sh.w), 0.f);
    ((float4*)x)[i] = v;
}

// ---------------- link prediction head ----------------
// out[e] = dot(x2[s], Wlin[0:128]) + dot(x2[d], Wlin[128:256]) + blin
__global__ void predict_kernel(const int* __restrict__ sidx,
                               const int* __restrict__ didx,
                               const float* __restrict__ Wlin,
                               const float* __restrict__ blin,
                               float* __restrict__ out, int EL) {
    int gw = (blockIdx.x * blockDim.x + threadIdx.x) >> 5;
    int lane = threadIdx.x & 31;
    if (gw >= EL) return;
    int s = __ldg(&sidx[gw]);
    int d = __ldg(&didx[gw]);
    float4 a = ((const float4*)g_x2)[(size_t)s * 32 + lane];
    float4 b = ((const float4*)g_x2)[(size_t)d * 32 + lane];
    float4 w1 = ((const float4*)Wlin)[lane];
    float4 w2 = ((const float4*)Wlin)[32 + lane];
    float p = a.x * w1.x + a.y * w1.y + a.z * w1.z + a.w * w1.w
            + b.x * w2.x + b.y * w2.y + b.z * w2.z + b.w * w2.w;
#pragma unroll
    for (int m = 16; m; m >>= 1) p += __shfl_xor_sync(0xffffffffu, p, m);
    if (lane == 0) out[gw] = p + blin[0];
}

// ---------------- launcher ----------------
extern "C" void kernel_launch(void* const* d_in, const int* in_sizes, int n_in,
                              void* d_out, int out_size) {
    const int*   edge_index = (const int*)d_in[0];     // [2, E]
    const int*   elabel     = (const int*)d_in[1];     // [2, EL]
    const float* emb        = (const float*)d_in[2];   // [N, 128]
    const float* Wl1  = (const float*)d_in[3];
    const float* bl1  = (const float*)d_in[4];
    const float* Wr1  = (const float*)d_in[5];
    const float* g1   = (const float*)d_in[6];
    const float* b1   = (const float*)d_in[7];
    const float* Wl2  = (const float*)d_in[8];
    const float* bl2  = (const float*)d_in[9];
    const float* Wr2  = (const float*)d_in[10];
    const float* g2   = (const float*)d_in[11];
    const float* b2   = (const float*)d_in[12];
    const float* Wlin = (const float*)d_in[13];
    const float* blin = (const float*)d_in[14];

    const int E  = in_sizes[0] / 2;
    const int EL = in_sizes[1] / 2;
    const int n  = in_sizes[2] / DD;
    float* out = (float*)d_out;

    cudaFuncSetAttribute(sage_kernel, cudaFuncAttributeMaxDynamicSharedMemorySize, 196608);

    void *p_x1 = nullptr, *p_x2 = nullptr;
    cudaGetSymbolAddress(&p_x1, g_x1);
    cudaGetSymbolAddress(&p_x2, g_x2);
    float* x1 = (float*)p_x1;
    float* x2 = (float*)p_x2;

    const int zblocks = (NN * DD / 4 + 255) / 256;
    const int sblocks = (E + 7) / 8;       // 8 warps per 256-thread block, 1 warp/edge
    const int gblocks = (n + 63) / 64;
    const int ablocks = (n * (DD / 4) + 255) / 256;
    const int pblocks = (EL + 7) / 8;

    // ---- layer 1 ----
    zero_kernel<<<zblocks, 256>>>(1);
    scatter_kernel<<<sblocks, 256>>>(emb, edge_index, edge_index + E, E, 1);
    sage_kernel<<<gblocks, 128, 196608>>>(emb, Wl1, bl1, Wr1, x1, n);
    bnparams_kernel<<<1, 128>>>(g1, b1, 1.0f / (float)n);
    bnrelu_kernel<<<ablocks, 256>>>(x1, n * (DD / 4));

    // ---- layer 2 ----
    zero_kernel<<<zblocks, 256>>>(0);
    scatter_kernel<<<sblocks, 256>>>(x1, edge_index, edge_index + E, E, 0);
    sage_kernel<<<gblocks, 128, 196608>>>(x1, Wl2, bl2, Wr2, x2, n);
    bnparams_kernel<<<1, 128>>>(g2, b2, 1.0f / (float)n);
    bnrelu_kernel<<<ablocks, 256>>>(x2, n * (DD / 4));

    // ---- head ----
    predict_kernel<<<pblocks, 256>>>(elabel, elabel + EL, Wlin, blin, out, EL);
}

// round 3
// speedup vs baseline: 1.1501x; 1.1501x over previous
#include <cuda_runtime.h>
#include <math.h>

// Problem constants (fixed by the dataset)
#define NN 100000   // nodes
#define DD 128      // feature dim (= hidden dim)
#define EE 1600000  // edges

// ---------------- scratch (static device globals; no allocation) ----------------
__device__ __align__(16) float g_agg[NN * DD];
__device__ __align__(16) float g_x1[NN * DD];
__device__ __align__(16) float g_x2[NN * DD];
__device__ int   g_deg[NN];
__device__ int   g_off[NN + 1];
__device__ int   g_cursor[NN];
__device__ int   g_csr[EE];
__device__ float g_bnsum[2 * DD];
__device__ float g_bnsq[2 * DD];
__device__ float g_scale[DD];
__device__ float g_shift[DD];
__device__ float g_p1[NN];
__device__ float g_p2[NN];

// ---------------- init: zero deg + BN accumulators ----------------
__global__ void init_kernel() {
    int i = blockIdx.x * blockDim.x + threadIdx.x;
    if (i < NN) g_deg[i] = 0;
    if (i < 2 * DD) { g_bnsum[i] = 0.f; g_bnsq[i] = 0.f; }
}

// ---------------- degree histogram ----------------
__global__ void hist_kernel(const int* __restrict__ dst, int E) {
    int i = blockIdx.x * blockDim.x + threadIdx.x;
    if (i < E) atomicAdd(&g_deg[__ldg(&dst[i])], 1);
}

// ---------------- single-block exclusive scan over 100K degrees ----------------
__global__ void scan_kernel() {
    __shared__ int sdata[1024];
    const int t = threadIdx.x;           // 1024 threads
    const int C = (NN + 1023) / 1024;    // 98
    const int beg = t * C;
    const int end = min(beg + C, NN);

    int psum = 0;
    for (int i = beg; i < end; i++) psum += g_deg[i];
    sdata[t] = psum;
    __syncthreads();

    // inclusive Hillis-Steele scan
    for (int d = 1; d < 1024; d <<= 1) {
        int v = (t >= d) ? sdata[t - d] : 0;
        __syncthreads();
        sdata[t] += v;
        __syncthreads();
    }
    int run = sdata[t] - psum;  // exclusive prefix for this chunk

    for (int i = beg; i < end; i++) {
        g_off[i] = run;
        g_cursor[i] = run;
        run += g_deg[i];
    }
    if (beg <= NN && NN < beg + C) g_off[NN] = run;
}

// ---------------- fill CSR: csr[slot] = src, keyed by dst ----------------
__global__ void fill_kernel(const int* __restrict__ src,
                            const int* __restrict__ dst, int E) {
    int i = blockIdx.x * blockDim.x + threadIdx.x;
    if (i >= E) return;
    int d = __ldg(&dst[i]);
    int slot = atomicAdd(&g_cursor[d], 1);
    g_csr[slot] = __ldg(&src[i]);
}

// ---------------- pull aggregation: agg[n] = mean of x[neighbors(n)] ----------------
// One warp per node; each lane owns a float4 (16B) slice of the 512B row.
__global__ void aggregate_kernel(const float* __restrict__ x) {
    int n = (blockIdx.x * blockDim.x + threadIdx.x) >> 5;
    int lane = threadIdx.x & 31;
    if (n >= NN) return;
    int beg = __ldg(&g_off[n]);
    int end = __ldg(&g_off[n + 1]);
    const float4* x4 = (const float4*)x;
    float4 acc = make_float4(0.f, 0.f, 0.f, 0.f);
    int j = beg;
    for (; j + 4 <= end; j += 4) {
        int s0 = __ldg(&g_csr[j]);
        int s1 = __ldg(&g_csr[j + 1]);
        int s2 = __ldg(&g_csr[j + 2]);
        int s3 = __ldg(&g_csr[j + 3]);
        float4 v0 = __ldg(&x4[(size_t)s0 * 32 + lane]);
        float4 v1 = __ldg(&x4[(size_t)s1 * 32 + lane]);
        float4 v2 = __ldg(&x4[(size_t)s2 * 32 + lane]);
        float4 v3 = __ldg(&x4[(size_t)s3 * 32 + lane]);
        acc.x += v0.x + v1.x + v2.x + v3.x;
        acc.y += v0.y + v1.y + v2.y + v3.y;
        acc.z += v0.z + v1.z + v2.z + v3.z;
        acc.w += v0.w + v1.w + v2.w + v3.w;
    }
    for (; j < end; j++) {
        int s = __ldg(&g_csr[j]);
        float4 v = __ldg(&x4[(size_t)s * 32 + lane]);
        acc.x += v.x; acc.y += v.y; acc.z += v.z; acc.w += v.w;
    }
    float inv = 1.0f / fmaxf((float)(end - beg), 1.0f);
    acc.x *= inv; acc.y *= inv; acc.z *= inv; acc.w *= inv;
    ((float4*)g_agg)[(size_t)n * 32 + lane] = acc;
}

// ---------------- fused SAGE layer ----------------
// out = L2normalize( agg @ Wl + bl + x @ Wr ), accumulates BN sum/sumsq.
// Block: 128 threads, 64-node tile, each thread computes an 8(nodes)x8(h) register tile.
__global__ void sage_kernel(const float* __restrict__ x_in,
                            const float* __restrict__ Wl,
                            const float* __restrict__ bl,
                            const float* __restrict__ Wr,
                            float* __restrict__ x_out,
                            int nnodes, int bn_slot) {
    extern __shared__ float sm[];
    float* Wl_s = sm;                 // 16384 floats, [d][h]
    float* Wr_s = sm + 16384;         // 16384 floats
    float* A_s  = sm + 32768;         // 8192 floats, [d][n] (n fastest)
    float* X_s  = sm + 40960;         // 8192 floats

    const int tid = threadIdx.x;      // 128 threads
    const int base = blockIdx.x * 64;

    const float4* Wl4 = (const float4*)Wl;
    const float4* Wr4 = (const float4*)Wr;
    float4* Wl_s4 = (float4*)Wl_s;
    float4* Wr_s4 = (float4*)Wr_s;
#pragma unroll
    for (int i = 0; i < 32; i++) {
        int q = tid + i * 128;
        Wl_s4[q] = Wl4[q];
        Wr_s4[q] = Wr4[q];
    }

#pragma unroll
    for (int i = 0; i < 16; i++) {
        int q = tid + i * 128;        // float4 granules
        int n = q >> 5;               // node within tile (0..63)
        int d4 = q & 31;              // float4 index along d
        int gn = base + n;
        float4 a = make_float4(0.f, 0.f, 0.f, 0.f);
        float4 xv = make_float4(0.f, 0.f, 0.f, 0.f);
        if (gn < nnodes) {
            a  = ((const float4*)g_agg)[(size_t)gn * 32 + d4];
            xv = ((const float4*)x_in)[(size_t)gn * 32 + d4];
        }
        int db = d4 * 4;
        A_s[(db + 0) * 64 + n] = a.x;
        A_s[(db + 1) * 64 + n] = a.y;
        A_s[(db + 2) * 64 + n] = a.z;
        A_s[(db + 3) * 64 + n] = a.w;
        X_s[(db + 0) * 64 + n] = xv.x;
        X_s[(db + 1) * 64 + n] = xv.y;
        X_s[(db + 2) * 64 + n] = xv.z;
        X_s[(db + 3) * 64 + n] = xv.w;
    }
    __syncthreads();

    const int tx = tid & 15;          // h tile
    const int ty = tid >> 4;          // n tile
    const int h0 = tx * 8;
    const int n0 = ty * 8;

    float acc[64];
#pragma unroll
    for (int i = 0; i < 64; i++) acc[i] = 0.f;

#pragma unroll 2
    for (int d = 0; d < 128; d++) {
        float4 wl0 = *(const float4*)(Wl_s + d * 128 + h0);
        float4 wl1 = *(const float4*)(Wl_s + d * 128 + h0 + 4);
        float4 wr0 = *(const float4*)(Wr_s + d * 128 + h0);
        float4 wr1 = *(const float4*)(Wr_s + d * 128 + h0 + 4);
        float4 a0  = *(const float4*)(A_s + d * 64 + n0);
        float4 a1  = *(const float4*)(A_s + d * 64 + n0 + 4);
        float4 xx0 = *(const float4*)(X_s + d * 64 + n0);
        float4 xx1 = *(const float4*)(X_s + d * 64 + n0 + 4);
        float ww[8] = {wl0.x, wl0.y, wl0.z, wl0.w, wl1.x, wl1.y, wl1.z, wl1.w};
        float uu[8] = {wr0.x, wr0.y, wr0.z, wr0.w, wr1.x, wr1.y, wr1.z, wr1.w};
        float aa[8] = {a0.x, a0.y, a0.z, a0.w, a1.x, a1.y, a1.z, a1.w};
        float xv[8] = {xx0.x, xx0.y, xx0.z, xx0.w, xx1.x, xx1.y, xx1.z, xx1.w};
#pragma unroll
        for (int ni = 0; ni < 8; ni++)
#pragma unroll
            for (int hi = 0; hi < 8; hi++)
                acc[ni * 8 + hi] += aa[ni] * ww[hi] + xv[ni] * uu[hi];
    }

    float bv[8];
#pragma unroll
    for (int hi = 0; hi < 8; hi++) bv[hi] = bl[h0 + hi];

    float p1[8], p2[8];
#pragma unroll
    for (int hi = 0; hi < 8; hi++) { p1[hi] = 0.f; p2[hi] = 0.f; }

#pragma unroll
    for (int ni = 0; ni < 8; ni++) {
        float v[8];
        float ss = 0.f;
#pragma unroll
        for (int hi = 0; hi < 8; hi++) {
            v[hi] = acc[ni * 8 + hi] + bv[hi];
            ss += v[hi] * v[hi];
        }
#pragma unroll
        for (int m = 1; m < 16; m <<= 1) ss += __shfl_xor_sync(0xffffffffu, ss, m);
        float inv = 1.0f / fmaxf(sqrtf(ss), 1e-12f);
        int gn = base + n0 + ni;
        if (gn < nnodes) {
            float4 o0 = make_float4(v[0] * inv, v[1] * inv, v[2] * inv, v[3] * inv);
            float4 o1 = make_float4(v[4] * inv, v[5] * inv, v[6] * inv, v[7] * inv);
            float4* op = (float4*)(x_out + (size_t)gn * DD + h0);
            op[0] = o0;
            op[1] = o1;
#pragma unroll
            for (int hi = 0; hi < 8; hi++) {
                float vo = v[hi] * inv;
                p1[hi] += vo;
                p2[hi] += vo * vo;
            }
        }
    }

    __syncthreads();
#pragma unroll
    for (int hi = 0; hi < 8; hi++) {
        A_s[(h0 + hi) * 8 + ty] = p1[hi];
        X_s[(h0 + hi) * 8 + ty] = p2[hi];
    }
    __syncthreads();
    {
        float s1 = 0.f, s2 = 0.f;
#pragma unroll
        for (int t = 0; t < 8; t++) {
            s1 += A_s[tid * 8 + t];
            s2 += X_s[tid * 8 + t];
        }
        atomicAdd(&g_bnsum[bn_slot * DD + tid], s1);
        atomicAdd(&g_bnsq[bn_slot * DD + tid], s2);
    }
}

// ---------------- BN params from accumulated sums ----------------
__global__ void bnparams_kernel(const float* __restrict__ g,
                                const float* __restrict__ b,
                                float invN, int bn_slot) {
    int h = threadIdx.x;
    float mean = g_bnsum[bn_slot * DD + h] * invN;
    float var = g_bnsq[bn_slot * DD + h] * invN - mean * mean;
    float sc = g[h] / sqrtf(var + 1e-5f);
    g_scale[h] = sc;
    g_shift[h] = b[h] - mean * sc;
}

// ---------------- apply BN + ReLU in place ----------------
__global__ void bnrelu_kernel(float* __restrict__ x, int total4) {
    int i = blockIdx.x * blockDim.x + threadIdx.x;
    if (i >= total4) return;
    int h4 = i & 31;
    float4 v = ((float4*)x)[i];
    float4 sc = ((const float4*)g_scale)[h4];
    float4 sh = ((const float4*)g_shift)[h4];
    v.x = fmaxf(fmaf(v.x, sc.x, sh.x), 0.f);
    v.y = fmaxf(fmaf(v.y, sc.y, sh.y), 0.f);
    v.z = fmaxf(fmaf(v.z, sc.z, sh.z), 0.f);
    v.w = fmaxf(fmaf(v.w, sc.w, sh.w), 0.f);
    ((float4*)x)[i] = v;
}

// ---------------- per-node dots for the prediction head ----------------
// p1[n] = dot(x2[n], Wlin[0:128]); p2[n] = dot(x2[n], Wlin[128:256])
__global__ void nodedots_kernel(const float* __restrict__ Wlin) {
    int n = (blockIdx.x * blockDim.x + threadIdx.x) >> 5;
    int lane = threadIdx.x & 31;
    if (n >= NN) return;
    float4 a = ((const float4*)g_x2)[(size_t)n * 32 + lane];
    float4 w1 = __ldg(&((const float4*)Wlin)[lane]);
    float4 w2 = __ldg(&((const float4*)Wlin)[32 + lane]);
    float p = a.x * w1.x + a.y * w1.y + a.z * w1.z + a.w * w1.w;
    float q = a.x * w2.x + a.y * w2.y + a.z * w2.z + a.w * w2.w;
#pragma unroll
    for (int m = 16; m; m >>= 1) {
        p += __shfl_xor_sync(0xffffffffu, p, m);
        q += __shfl_xor_sync(0xffffffffu, q, m);
    }
    if (lane == 0) { g_p1[n] = p; g_p2[n] = q; }
}

// ---------------- final prediction: out[e] = p1[s] + p2[d] + blin ----------------
__global__ void predict_kernel(const int* __restrict__ sidx,
                               const int* __restrict__ didx,
                               const float* __restrict__ blin,
                               float* __restrict__ out, int EL) {
    int i = blockIdx.x * blockDim.x + threadIdx.x;
    if (i >= EL) return;
    int s = __ldg(&sidx[i]);
    int d = __ldg(&didx[i]);
    out[i] = g_p1[s] + g_p2[d] + blin[0];
}

// ---------------- launcher ----------------
extern "C" void kernel_launch(void* const* d_in, const int* in_sizes, int n_in,
                              void* d_out, int out_size) {
    const int*   edge_index = (const int*)d_in[0];     // [2, E]
    const int*   elabel     = (const int*)d_in[1];     // [2, EL]
    const float* emb        = (const float*)d_in[2];   // [N, 128]
    const float* Wl1  = (const float*)d_in[3];
    const float* bl1  = (const float*)d_in[4];
    const float* Wr1  = (const float*)d_in[5];
    const float* g1   = (const float*)d_in[6];
    const float* b1   = (const float*)d_in[7];
    const float* Wl2  = (const float*)d_in[8];
    const float* bl2  = (const float*)d_in[9];
    const float* Wr2  = (const float*)d_in[10];
    const float* g2   = (const float*)d_in[11];
    const float* b2   = (const float*)d_in[12];
    const float* Wlin = (const float*)d_in[13];
    const float* blin = (const float*)d_in[14];

    const int E  = in_sizes[0] / 2;
    const int EL = in_sizes[1] / 2;
    const int n  = in_sizes[2] / DD;
    float* out = (float*)d_out;

    cudaFuncSetAttribute(sage_kernel, cudaFuncAttributeMaxDynamicSharedMemorySize, 196608);

    void *p_x1 = nullptr, *p_x2 = nullptr;
    cudaGetSymbolAddress(&p_x1, g_x1);
    cudaGetSymbolAddress(&p_x2, g_x2);
    float* x1 = (float*)p_x1;
    float* x2 = (float*)p_x2;

    const int eblocks = (E + 255) / 256;
    const int gblocks = (n + 63) / 64;
    const int ablocks = (n * (DD / 4) + 255) / 256;
    const int wblocks = (n + 7) / 8;       // warp-per-node kernels, 8 warps/block
    const float invN = 1.0f / (float)n;

    // ---- CSR build (once; reused by both layers) ----
    init_kernel<<<(NN + 255) / 256, 256>>>();
    hist_kernel<<<eblocks, 256>>>(edge_index + E, E);
    scan_kernel<<<1, 1024>>>();
    fill_kernel<<<eblocks, 256>>>(edge_index, edge_index + E, E);

    // ---- layer 1 ----
    aggregate_kernel<<<wblocks, 256>>>(emb);
    sage_kernel<<<gblocks, 128, 196608>>>(emb, Wl1, bl1, Wr1, x1, n, 0);
    bnparams_kernel<<<1, 128>>>(g1, b1, invN, 0);
    bnrelu_kernel<<<ablocks, 256>>>(x1, n * (DD / 4));

    // ---- layer 2 ----
    aggregate_kernel<<<wblocks, 256>>>(x1);
    sage_kernel<<<gblocks, 128, 196608>>>(x1, Wl2, bl2, Wr2, x2, n, 1);
    bnparams_kernel<<<1, 128>>>(g2, b2, invN, 1);
    bnrelu_kernel<<<ablocks, 256>>>(x2, n * (DD / 4));

    // ---- head ----
    nodedots_kernel<<<wblocks, 256>>>(Wlin);
    predict_kernel<<<(EL + 255) / 256, 256>>>(elabel, elabel + EL, blin, out, EL);
}

// round 4
// speedup vs baseline: 2.2067x; 1.9186x over previous
#include <cuda_runtime.h>
#include <math.h>
#include <stdint.h>

// Problem constants (fixed by the dataset)
#define NN 100000   // nodes
#define DD 128      // feature dim (= hidden dim)
#define EE 1600000  // edges

// ---------------- scratch (static device globals; no allocation) ----------------
__device__ __align__(16) float g_agg[NN * DD];
__device__ __align__(16) float g_x1[NN * DD];
__device__ __align__(16) float g_x2[NN * DD];
__device__ int   g_deg[NN];
__device__ int   g_off[NN + 1];
__device__ int   g_cursor[NN];
__device__ int   g_csr[EE];
__device__ float g_bnsum[2 * DD];
__device__ float g_bnsq[2 * DD];
__device__ float g_scale[DD];
__device__ float g_shift[DD];
__device__ float g_p1[NN];
__device__ float g_p2[NN];

// ---------------- init: zero deg + BN accumulators ----------------
__global__ void init_kernel() {
    int i = blockIdx.x * blockDim.x + threadIdx.x;
    if (i < NN) g_deg[i] = 0;
    if (i < 2 * DD) { g_bnsum[i] = 0.f; g_bnsq[i] = 0.f; }
}

// ---------------- degree histogram ----------------
__global__ void hist_kernel(const int* __restrict__ dst, int E) {
    int i = blockIdx.x * blockDim.x + threadIdx.x;
    if (i < E) atomicAdd(&g_deg[__ldg(&dst[i])], 1);
}

// ---------------- single-block exclusive scan over 100K degrees ----------------
__global__ void scan_kernel() {
    __shared__ int sdata[1024];
    const int t = threadIdx.x;           // 1024 threads
    const int C = (NN + 1023) / 1024;
    const int beg = t * C;
    const int end = min(beg + C, NN);

    int psum = 0;
    for (int i = beg; i < end; i++) psum += g_deg[i];
    sdata[t] = psum;
    __syncthreads();

    for (int d = 1; d < 1024; d <<= 1) {
        int v = (t >= d) ? sdata[t - d] : 0;
        __syncthreads();
        sdata[t] += v;
        __syncthreads();
    }
    int run = sdata[t] - psum;  // exclusive prefix

    for (int i = beg; i < end; i++) {
        g_off[i] = run;
        g_cursor[i] = run;
        run += g_deg[i];
    }
    if (beg <= NN && NN < beg + C) g_off[NN] = run;
}

// ---------------- fill CSR: csr[slot] = src, keyed by dst ----------------
__global__ void fill_kernel(const int* __restrict__ src,
                            const int* __restrict__ dst, int E) {
    int i = blockIdx.x * blockDim.x + threadIdx.x;
    if (i >= E) return;
    int d = __ldg(&dst[i]);
    int slot = atomicAdd(&g_cursor[d], 1);
    g_csr[slot] = __ldg(&src[i]);
}

// ---------------- pull aggregation: agg[n] = mean of x[neighbors(n)] ----------------
__global__ void aggregate_kernel(const float* __restrict__ x) {
    int n = (blockIdx.x * blockDim.x + threadIdx.x) >> 5;
    int lane = threadIdx.x & 31;
    if (n >= NN) return;
    int beg = __ldg(&g_off[n]);
    int end = __ldg(&g_off[n + 1]);
    const float4* x4 = (const float4*)x;
    float4 acc = make_float4(0.f, 0.f, 0.f, 0.f);
    int j = beg;
    for (; j + 4 <= end; j += 4) {
        int s0 = __ldg(&g_csr[j]);
        int s1 = __ldg(&g_csr[j + 1]);
        int s2 = __ldg(&g_csr[j + 2]);
        int s3 = __ldg(&g_csr[j + 3]);
        float4 v0 = __ldg(&x4[(size_t)s0 * 32 + lane]);
        float4 v1 = __ldg(&x4[(size_t)s1 * 32 + lane]);
        float4 v2 = __ldg(&x4[(size_t)s2 * 32 + lane]);
        float4 v3 = __ldg(&x4[(size_t)s3 * 32 + lane]);
        acc.x += v0.x + v1.x + v2.x + v3.x;
        acc.y += v0.y + v1.y + v2.y + v3.y;
        acc.z += v0.z + v1.z + v2.z + v3.z;
        acc.w += v0.w + v1.w + v2.w + v3.w;
    }
    for (; j < end; j++) {
        int s = __ldg(&g_csr[j]);
        float4 v = __ldg(&x4[(size_t)s * 32 + lane]);
        acc.x += v.x; acc.y += v.y; acc.z += v.z; acc.w += v.w;
    }
    float inv = 1.0f / fmaxf((float)(end - beg), 1.0f);
    acc.x *= inv; acc.y *= inv; acc.z *= inv; acc.w *= inv;
    ((float4*)g_agg)[(size_t)n * 32 + lane] = acc;
}

// ---------------- tf32 helpers ----------------
__device__ __forceinline__ void split_tf32(float v, uint32_t& hi, uint32_t& lo) {
    uint32_t uh = __float_as_uint(v) & 0xFFFFE000u;   // truncate to tf32
    float fl = v - __uint_as_float(uh);               // exact residual
    hi = uh;
    lo = __float_as_uint(fl) & 0xFFFFE000u;
}

__device__ __forceinline__ void mma_tf32(float c[4],
                                         uint32_t a0, uint32_t a1, uint32_t a2, uint32_t a3,
                                         uint32_t b0, uint32_t b1) {
    asm volatile(
        "mma.sync.aligned.m16n8k8.row.col.f32.tf32.tf32.f32 "
        "{%0,%1,%2,%3}, {%4,%5,%6,%7}, {%8,%9}, {%0,%1,%2,%3};"
        : "+f"(c[0]), "+f"(c[1]), "+f"(c[2]), "+f"(c[3])
        : "r"(a0), "r"(a1), "r"(a2), "r"(a3), "r"(b0), "r"(b1));
}

// ---------------- fused SAGE layer (tensor cores, 3xTF32) ----------------
// out = L2normalize( [agg|x] @ [Wl;Wr] + bl ), accumulates BN sum/sumsq.
// Block: 256 threads (8 warps), 128-node x 128-h tile, K=256 in 8 chunks of 32.
// Warp tile: 32(M) x 64(N) = 2 x 8 m16n8k8 tiles.
#define AX_STRIDE 36
#define W_STRIDE 136
#define SAGE_SMEM ((2 * 128 * AX_STRIDE + 2 * 32 * W_STRIDE + 256 + 128 + 128) * 4)

__global__ void __launch_bounds__(256, 2)
sage_mma_kernel(const float* __restrict__ x_in,
                const float* __restrict__ Wl,
                const float* __restrict__ bl,
                const float* __restrict__ Wr,
                float* __restrict__ x_out,
                int nnodes, int bn_slot) {
    extern __shared__ uint32_t sm[];
    uint32_t* AXhi = sm;                          // [128][36]
    uint32_t* AXlo = AXhi + 128 * AX_STRIDE;
    uint32_t* Whi  = AXlo + 128 * AX_STRIDE;      // [32][136]
    uint32_t* Wlo  = Whi + 32 * W_STRIDE;
    float* rowsumS = (float*)(Wlo + 32 * W_STRIDE);  // [128][2]
    float* colsumS = rowsumS + 256;               // [128]
    float* colsqS  = colsumS + 128;               // [128]

    const int tid = threadIdx.x;
    const int wid = tid >> 5;
    const int lane = tid & 31;
    const int g = lane >> 2;
    const int t = lane & 3;
    const int warp_m = wid & 3;      // 4 M-warps of 32 rows
    const int warp_n = wid >> 2;     // 2 N-warps of 64 cols
    const int base = blockIdx.x * 128;

    if (tid < 128) { colsumS[tid] = 0.f; colsqS[tid] = 0.f; }

    float c[2][8][4];
#pragma unroll
    for (int mt = 0; mt < 2; mt++)
#pragma unroll
        for (int nt = 0; nt < 8; nt++)
#pragma unroll
            for (int k = 0; k < 4; k++) c[mt][nt][k] = 0.f;

    for (int chunk = 0; chunk < 8; chunk++) {
        const int kBase = chunk * 32;
        // ---- stage AX chunk: rows 0..127, cols kBase..kBase+31 (A for k<128, X after) ----
        const float* srcA = (kBase < 128) ? (g_agg + (size_t)base * DD + kBase)
                                          : (x_in + (size_t)base * DD + (kBase - 128));
#pragma unroll
        for (int i = 0; i < 4; i++) {
            int q = tid + i * 256;          // 0..1023 float4 granules
            int row = q >> 3;
            int f4 = q & 7;
            int grow = base + row;
            float4 v = make_float4(0.f, 0.f, 0.f, 0.f);
            if (grow < nnodes)
                v = __ldg((const float4*)(srcA + (size_t)row * DD) + f4);
            int col = f4 * 4;
            uint32_t h0, l0, h1, l1, h2, l2, h3, l3;
            split_tf32(v.x, h0, l0); split_tf32(v.y, h1, l1);
            split_tf32(v.z, h2, l2); split_tf32(v.w, h3, l3);
            uint32_t* ph = AXhi + row * AX_STRIDE + col;
            uint32_t* pl = AXlo + row * AX_STRIDE + col;
            ph[0] = h0; ph[1] = h1; ph[2] = h2; ph[3] = h3;
            pl[0] = l0; pl[1] = l1; pl[2] = l2; pl[3] = l3;
        }
        // ---- stage W chunk: rows kBase..+31 of [Wl;Wr], all 128 cols ----
        const float* srcW = (kBase < 128) ? (Wl + (size_t)kBase * DD)
                                          : (Wr + (size_t)(kBase - 128) * DD);
#pragma unroll
        for (int i = 0; i < 4; i++) {
            int q = tid + i * 256;          // 0..1023 float4 granules (32 rows x 32 f4)
            int kk = q >> 5;
            int f4 = q & 31;
            float4 v = __ldg((const float4*)(srcW + (size_t)kk * DD) + f4);
            int col = f4 * 4;
            uint32_t h0, l0, h1, l1, h2, l2, h3, l3;
            split_tf32(v.x, h0, l0); split_tf32(v.y, h1, l1);
            split_tf32(v.z, h2, l2); split_tf32(v.w, h3, l3);
            uint32_t* ph = Whi + kk * W_STRIDE + col;
            uint32_t* pl = Wlo + kk * W_STRIDE + col;
            ph[0] = h0; ph[1] = h1; ph[2] = h2; ph[3] = h3;
            pl[0] = l0; pl[1] = l1; pl[2] = l2; pl[3] = l3;
        }
        __syncthreads();

        // ---- compute 4 k-steps of 8 ----
#pragma unroll
        for (int ks = 0; ks < 4; ks++) {
            const int kk = ks * 8;
            uint32_t ahi[2][4], alo[2][4];
#pragma unroll
            for (int mt = 0; mt < 2; mt++) {
                int r = warp_m * 32 + mt * 16 + g;
                ahi[mt][0] = AXhi[r * AX_STRIDE + kk + t];
                ahi[mt][1] = AXhi[(r + 8) * AX_STRIDE + kk + t];
                ahi[mt][2] = AXhi[r * AX_STRIDE + kk + t + 4];
                ahi[mt][3] = AXhi[(r + 8) * AX_STRIDE + kk + t + 4];
                alo[mt][0] = AXlo[r * AX_STRIDE + kk + t];
                alo[mt][1] = AXlo[(r + 8) * AX_STRIDE + kk + t];
                alo[mt][2] = AXlo[r * AX_STRIDE + kk + t + 4];
                alo[mt][3] = AXlo[(r + 8) * AX_STRIDE + kk + t + 4];
            }
#pragma unroll
            for (int nt = 0; nt < 8; nt++) {
                int cn = warp_n * 64 + nt * 8 + g;
                uint32_t bh0 = Whi[(kk + t) * W_STRIDE + cn];
                uint32_t bh1 = Whi[(kk + t + 4) * W_STRIDE + cn];
                uint32_t bl0 = Wlo[(kk + t) * W_STRIDE + cn];
                uint32_t bl1 = Wlo[(kk + t + 4) * W_STRIDE + cn];
#pragma unroll
                for (int mt = 0; mt < 2; mt++) {
                    mma_tf32(c[mt][nt], ahi[mt][0], ahi[mt][1], ahi[mt][2], ahi[mt][3], bh0, bh1);
                    mma_tf32(c[mt][nt], ahi[mt][0], ahi[mt][1], ahi[mt][2], ahi[mt][3], bl0, bl1);
                    mma_tf32(c[mt][nt], alo[mt][0], alo[mt][1], alo[mt][2], alo[mt][3], bh0, bh1);
                }
            }
        }
        __syncthreads();
    }

    // ---- epilogue: bias, row L2 norm, store, BN stats ----
#pragma unroll
    for (int nt = 0; nt < 8; nt++) {
        int cn = warp_n * 64 + nt * 8 + 2 * t;
        float b0v = __ldg(&bl[cn]);
        float b1v = __ldg(&bl[cn + 1]);
#pragma unroll
        for (int mt = 0; mt < 2; mt++) {
            c[mt][nt][0] += b0v; c[mt][nt][1] += b1v;
            c[mt][nt][2] += b0v; c[mt][nt][3] += b1v;
        }
    }

#pragma unroll
    for (int mt = 0; mt < 2; mt++) {
        float ssu = 0.f, ssd = 0.f;
#pragma unroll
        for (int nt = 0; nt < 8; nt++) {
            ssu += c[mt][nt][0] * c[mt][nt][0] + c[mt][nt][1] * c[mt][nt][1];
            ssd += c[mt][nt][2] * c[mt][nt][2] + c[mt][nt][3] * c[mt][nt][3];
        }
        ssu += __shfl_xor_sync(0xffffffffu, ssu, 1);
        ssu += __shfl_xor_sync(0xffffffffu, ssu, 2);
        ssd += __shfl_xor_sync(0xffffffffu, ssd, 1);
        ssd += __shfl_xor_sync(0xffffffffu, ssd, 2);
        if (t == 0) {
            int r = warp_m * 32 + mt * 16 + g;
            rowsumS[r * 2 + warp_n] = ssu;
            rowsumS[(r + 8) * 2 + warp_n] = ssd;
        }
    }
    __syncthreads();

    float p1[16], p2[16];
#pragma unroll
    for (int i = 0; i < 16; i++) { p1[i] = 0.f; p2[i] = 0.f; }

#pragma unroll
    for (int mt = 0; mt < 2; mt++) {
        int r_up = warp_m * 32 + mt * 16 + g;
        int r_dn = r_up + 8;
        float su = rowsumS[r_up * 2] + rowsumS[r_up * 2 + 1];
        float sd = rowsumS[r_dn * 2] + rowsumS[r_dn * 2 + 1];
        float invu = 1.0f / fmaxf(sqrtf(su), 1e-12f);
        float invd = 1.0f / fmaxf(sqrtf(sd), 1e-12f);
        int gu = base + r_up, gd = base + r_dn;
        bool vu = gu < nnodes, vd = gd < nnodes;
#pragma unroll
        for (int nt = 0; nt < 8; nt++) {
            int cn = warp_n * 64 + nt * 8 + 2 * t;
            if (vu) {
                float v0 = c[mt][nt][0] * invu, v1 = c[mt][nt][1] * invu;
                *(float2*)(x_out + (size_t)gu * DD + cn) = make_float2(v0, v1);
                p1[nt * 2] += v0; p2[nt * 2] += v0 * v0;
                p1[nt * 2 + 1] += v1; p2[nt * 2 + 1] += v1 * v1;
            }
            if (vd) {
                float v0 = c[mt][nt][2] * invd, v1 = c[mt][nt][3] * invd;
                *(float2*)(x_out + (size_t)gd * DD + cn) = make_float2(v0, v1);
                p1[nt * 2] += v0; p2[nt * 2] += v0 * v0;
                p1[nt * 2 + 1] += v1; p2[nt * 2 + 1] += v1 * v1;
            }
        }
    }

#pragma unroll
    for (int nt = 0; nt < 8; nt++) {
        int cn = warp_n * 64 + nt * 8 + 2 * t;
        atomicAdd(&colsumS[cn], p1[nt * 2]);
        atomicAdd(&colsqS[cn], p2[nt * 2]);
        atomicAdd(&colsumS[cn + 1], p1[nt * 2 + 1]);
        atomicAdd(&colsqS[cn + 1], p2[nt * 2 + 1]);
    }
    __syncthreads();
    if (tid < 128) {
        atomicAdd(&g_bnsum[bn_slot * DD + tid], colsumS[tid]);
        atomicAdd(&g_bnsq[bn_slot * DD + tid], colsqS[tid]);
    }
}

// ---------------- BN params from accumulated sums ----------------
__global__ void bnparams_kernel(const float* __restrict__ g,
                                const float* __restrict__ b,
                                float invN, int bn_slot) {
    int h = threadIdx.x;
    float mean = g_bnsum[bn_slot * DD + h] * invN;
    float var = g_bnsq[bn_slot * DD + h] * invN - mean * mean;
    float sc = g[h] / sqrtf(var + 1e-5f);
    g_scale[h] = sc;
    g_shift[h] = b[h] - mean * sc;
}

// ---------------- apply BN + ReLU in place ----------------
__global__ void bnrelu_kernel(float* __restrict__ x, int total4) {
    int i = blockIdx.x * blockDim.x + threadIdx.x;
    if (i >= total4) return;
    int h4 = i & 31;
    float4 v = ((float4*)x)[i];
    float4 sc = ((const float4*)g_scale)[h4];
    float4 sh = ((const float4*)g_shift)[h4];
    v.x = fmaxf(fmaf(v.x, sc.x, sh.x), 0.f);
    v.y = fmaxf(fmaf(v.y, sc.y, sh.y), 0.f);
    v.z = fmaxf(fmaf(v.z, sc.z, sh.z), 0.f);
    v.w = fmaxf(fmaf(v.w, sc.w, sh.w), 0.f);
    ((float4*)x)[i] = v;
}

// ---------------- per-node dots for the prediction head ----------------
__global__ void nodedots_kernel(const float* __restrict__ Wlin) {
    int n = (blockIdx.x * blockDim.x + threadIdx.x) >> 5;
    int lane = threadIdx.x & 31;
    if (n >= NN) return;
    float4 a = ((const float4*)g_x2)[(size_t)n * 32 + lane];
    float4 w1 = __ldg(&((const float4*)Wlin)[lane]);
    float4 w2 = __ldg(&((const float4*)Wlin)[32 + lane]);
    float p = a.x * w1.x + a.y * w1.y + a.z * w1.z + a.w * w1.w;
    float q = a.x * w2.x + a.y * w2.y + a.z * w2.z + a.w * w2.w;
#pragma unroll
    for (int m = 16; m; m >>= 1) {
        p += __shfl_xor_sync(0xffffffffu, p, m);
        q += __shfl_xor_sync(0xffffffffu, q, m);
    }
    if (lane == 0) { g_p1[n] = p; g_p2[n] = q; }
}

// ---------------- final prediction: out[e] = p1[s] + p2[d] + blin ----------------
__global__ void predict_kernel(const int* __restrict__ sidx,
                               const int* __restrict__ didx,
                               const float* __restrict__ blin,
                               float* __restrict__ out, int EL) {
    int i = blockIdx.x * blockDim.x + threadIdx.x;
    if (i >= EL) return;
    int s = __ldg(&sidx[i]);
    int d = __ldg(&didx[i]);
    out[i] = g_p1[s] + g_p2[d] + blin[0];
}

// ---------------- launcher ----------------
extern "C" void kernel_launch(void* const* d_in, const int* in_sizes, int n_in,
                              void* d_out, int out_size) {
    const int*   edge_index = (const int*)d_in[0];     // [2, E]
    const int*   elabel     = (const int*)d_in[1];     // [2, EL]
    const float* emb        = (const float*)d_in[2];   // [N, 128]
    const float* Wl1  = (const float*)d_in[3];
    const float* bl1  = (const float*)d_in[4];
    const float* Wr1  = (const float*)d_in[5];
    const float* g1   = (const float*)d_in[6];
    const float* b1   = (const float*)d_in[7];
    const float* Wl2  = (const float*)d_in[8];
    const float* bl2  = (const float*)d_in[9];
    const float* Wr2  = (const float*)d_in[10];
    const float* g2   = (const float*)d_in[11];
    const float* b2   = (const float*)d_in[12];
    const float* Wlin = (const float*)d_in[13];
    const float* blin = (const float*)d_in[14];

    const int E  = in_sizes[0] / 2;
    const int EL = in_sizes[1] / 2;
    const int n  = in_sizes[2] / DD;
    float* out = (float*)d_out;

    cudaFuncSetAttribute(sage_mma_kernel, cudaFuncAttributeMaxDynamicSharedMemorySize, SAGE_SMEM);

    void *p_x1 = nullptr, *p_x2 = nullptr;
    cudaGetSymbolAddress(&p_x1, g_x1);
    cudaGetSymbolAddress(&p_x2, g_x2);
    float* x1 = (float*)p_x1;
    float* x2 = (float*)p_x2;

    const int eblocks = (E + 255) / 256;
    const int gblocks = (n + 127) / 128;
    const int ablocks = (n * (DD / 4) + 255) / 256;
    const int wblocks = (n + 7) / 8;
    const float invN = 1.0f / (float)n;

    // ---- CSR build (once; reused by both layers) ----
    init_kernel<<<(NN + 255) / 256, 256>>>();
    hist_kernel<<<eblocks, 256>>>(edge_index + E, E);
    scan_kernel<<<1, 1024>>>();
    fill_kernel<<<eblocks, 256>>>(edge_index, edge_index + E, E);

    // ---- layer 1 ----
    aggregate_kernel<<<wblocks, 256>>>(emb);
    sage_mma_kernel<<<gblocks, 256, SAGE_SMEM>>>(emb, Wl1, bl1, Wr1, x1, n, 0);
    bnparams_kernel<<<1, 128>>>(g1, b1, invN, 0);
    bnrelu_kernel<<<ablocks, 256>>>(x1, n * (DD / 4));

    // ---- layer 2 ----
    aggregate_kernel<<<wblocks, 256>>>(x1);
    sage_mma_kernel<<<gblocks, 256, SAGE_SMEM>>>(x1, Wl2, bl2, Wr2, x2, n, 1);
    bnparams_kernel<<<1, 128>>>(g2, b2, invN, 1);
    bnrelu_kernel<<<ablocks, 256>>>(x2, n * (DD / 4));

    // ---- head ----
    nodedots_kernel<<<wblocks, 256>>>(Wlin);
    predict_kernel<<<(EL + 255) / 256, 256>>>(elabel, elabel + EL, blin, out, EL);
}